// round 5
// baseline (speedup 1.0000x reference)
#include <cuda_runtime.h>
#include <cuda_bf16.h>
#include <cstdint>
#include <cstddef>

// Problem constants (fixed by the dataset)
#define NP_ 100000
#define NQ_ 50000
#define D_  128
#define E_DEFAULT 600000

// ---------------------------------------------------------------------------
// Device scratch (static: no runtime allocation allowed)
// ---------------------------------------------------------------------------
__device__ float g_accP[(size_t)NP_ * D_];   // product->person aggregation accumulator
__device__ float g_accQ[(size_t)NQ_ * D_];   // person->product aggregation accumulator
__device__ float g_cntP[NP_];
__device__ float g_cntQ[NQ_];
__device__ float g_hP[(size_t)NP_ * D_];     // layer-0 person output (post ReLU)
__device__ float g_hQ[(size_t)NQ_ * D_];     // layer-0 product output (post ReLU)

// ---------------------------------------------------------------------------
// Helpers: packed f32x2 FMA (Blackwell), pack/unpack
// ---------------------------------------------------------------------------
__device__ __forceinline__ unsigned long long pack2(float a, float b) {
    unsigned long long r;
    asm("mov.b64 %0, {%1, %2};" : "=l"(r) : "f"(a), "f"(b));
    return r;
}
__device__ __forceinline__ void fma2(unsigned long long& acc,
                                     unsigned long long a,
                                     unsigned long long b) {
    asm("fma.rn.f32x2 %0, %1, %2, %0;" : "+l"(acc) : "l"(a), "l"(b));
}
__device__ __forceinline__ float2 unpack2(unsigned long long v) {
    float2 r;
    asm("mov.b64 {%0, %1}, %2;" : "=f"(r.x), "=f"(r.y) : "l"(v));
    return r;
}

// ---------------------------------------------------------------------------
// Zero accumulators + counts
// ---------------------------------------------------------------------------
__global__ void zero_kernel() {
    size_t i = (size_t)blockIdx.x * blockDim.x + threadIdx.x;
    size_t stride = (size_t)gridDim.x * blockDim.x;
    float4 z = make_float4(0.f, 0.f, 0.f, 0.f);
    float4* aP = reinterpret_cast<float4*>(g_accP);
    float4* aQ = reinterpret_cast<float4*>(g_accQ);
    const size_t nP4 = (size_t)NP_ * (D_ / 4);
    const size_t nQ4 = (size_t)NQ_ * (D_ / 4);
    for (size_t k = i; k < nP4; k += stride) aP[k] = z;
    for (size_t k = i; k < nQ4; k += stride) aQ[k] = z;
    for (size_t k = i; k < NP_; k += stride) g_cntP[k] = 0.f;
    for (size_t k = i; k < NQ_; k += stride) g_cntQ[k] = 0.f;
}

// ---------------------------------------------------------------------------
// Scatter-add: one warp per edge.
//   TO_Q:  accumulate into product side (g_accQ) else person side (g_accP)
//   SRC_H: gather from layer-0 hidden state instead of the kernel-arg x.
// Each lane moves one float4 (row = 32 lanes * 16B = 512B), vector RED.
// ---------------------------------------------------------------------------
template <bool TO_Q, bool SRC_H>
__global__ __launch_bounds__(256) void scatter_kernel(
    const float* __restrict__ xin,
    const int* __restrict__ src,
    const int* __restrict__ dst,
    int nE)
{
    const float* x = SRC_H ? (TO_Q ? g_hP : g_hQ) : xin;
    float* acc = TO_Q ? g_accQ : g_accP;
    float* cnt = TO_Q ? g_cntQ : g_cntP;

    int warp = (int)((blockIdx.x * blockDim.x + threadIdx.x) >> 5);
    int lane = threadIdx.x & 31;
    if (warp >= nE) return;

    int s = __ldg(src + warp);
    int d = __ldg(dst + warp);

    float4 v = *reinterpret_cast<const float4*>(x + (size_t)s * D_ + lane * 4);
    float* p = acc + (size_t)d * D_ + lane * 4;
    asm volatile("red.global.add.v4.f32 [%0], {%1, %2, %3, %4};"
                 :: "l"(p), "f"(v.x), "f"(v.y), "f"(v.z), "f"(v.w)
                 : "memory");
    if (lane == 0) atomicAdd(cnt + d, 1.0f);
}

// ---------------------------------------------------------------------------
// Fused SAGE linear:  out = (acc/max(cnt,1)) @ Wl + self @ Wr + b  [+ReLU]
// Tile: 128 rows x 128 cols, 256 threads, 8x8 microtile, K folded as two
// 128-deep passes (Wl over scaled acc, then Wr over self features).
//   Q_SIDE: operate on product rows (g_accQ/g_cntQ) else person rows.
//   LAYER1: self comes from g_h*, output goes to the kernel-arg pointer,
//           no ReLU. Otherwise self is the kernel-arg x, output to g_h*,
//           ReLU applied.
// ---------------------------------------------------------------------------
#define BM 128
#define BK 16

template <bool Q_SIDE, bool LAYER1>
__global__ __launch_bounds__(256) void gemm_kernel(
    const float* __restrict__ xparam,
    const float* __restrict__ Wl,
    const float* __restrict__ Wr,
    const float* __restrict__ bias,
    float* __restrict__ outparam,
    int nrows)
{
    const float* acc  = Q_SIDE ? g_accQ : g_accP;
    const float* cnt  = Q_SIDE ? g_cntQ : g_cntP;
    const float* self = LAYER1 ? (Q_SIDE ? g_hQ : g_hP) : xparam;
    float*       out  = LAYER1 ? outparam : (Q_SIDE ? g_hQ : g_hP);

    __shared__ float As[BK][BM + 4];
    __shared__ float Bs[BK][D_];
    __shared__ float rscale[BM];

    int tid = threadIdx.x;
    int tx = tid & 15;   // column group: cols tx*8 .. tx*8+7
    int ty = tid >> 4;   // row group:    rows ty*8 .. ty*8+7
    int row0 = blockIdx.x * BM;

    if (tid < BM) {
        int r = row0 + tid;
        float c = (r < nrows) ? cnt[r] : 1.f;
        rscale[tid] = 1.f / fmaxf(c, 1.f);
    }
    __syncthreads();

    unsigned long long accr[8][4];
#pragma unroll
    for (int i = 0; i < 8; i++)
#pragma unroll
        for (int j = 0; j < 4; j++) accr[i][j] = 0ull;

#pragma unroll
    for (int pass = 0; pass < 2; ++pass) {
        const float* A = pass ? self : acc;
        const float* W = pass ? Wr : Wl;
        for (int k0 = 0; k0 < D_; k0 += BK) {
            // ---- load A tile (128 rows x 16 k), transposed into As[k][m] ----
            {
                int q = tid;                 // first half
#pragma unroll
                for (int half = 0; half < 2; ++half, q += 256) {
                    int r  = q >> 2;         // local row 0..127
                    int kq = q & 3;          // float4 slot within the 16-wide k slice
                    int grow = row0 + r;
                    float4 v = make_float4(0.f, 0.f, 0.f, 0.f);
                    if (grow < nrows)
                        v = *reinterpret_cast<const float4*>(
                                A + (size_t)grow * D_ + k0 + kq * 4);
                    float sc = pass ? 1.f : rscale[r];
                    As[kq * 4 + 0][r] = v.x * sc;
                    As[kq * 4 + 1][r] = v.y * sc;
                    As[kq * 4 + 2][r] = v.z * sc;
                    As[kq * 4 + 3][r] = v.w * sc;
                }
            }
            // ---- load B tile (16 k x 128 n) ----
            {
                int q = tid;
#pragma unroll
                for (int half = 0; half < 2; ++half, q += 256) {
                    int kr = q >> 5;         // 0..15
                    int c4 = q & 31;         // float4 column slot
                    *reinterpret_cast<float4*>(&Bs[kr][c4 * 4]) =
                        *reinterpret_cast<const float4*>(
                            W + (size_t)(k0 + kr) * D_ + c4 * 4);
                }
            }
            __syncthreads();

#pragma unroll
            for (int kk = 0; kk < BK; ++kk) {
                float4 a0 = *reinterpret_cast<const float4*>(&As[kk][ty * 8]);
                float4 a1 = *reinterpret_cast<const float4*>(&As[kk][ty * 8 + 4]);
                float4 b0 = *reinterpret_cast<const float4*>(&Bs[kk][tx * 8]);
                float4 b1 = *reinterpret_cast<const float4*>(&Bs[kk][tx * 8 + 4]);
                unsigned long long bp0 = pack2(b0.x, b0.y);
                unsigned long long bp1 = pack2(b0.z, b0.w);
                unsigned long long bp2 = pack2(b1.x, b1.y);
                unsigned long long bp3 = pack2(b1.z, b1.w);
                float av[8] = {a0.x, a0.y, a0.z, a0.w, a1.x, a1.y, a1.z, a1.w};
#pragma unroll
                for (int i = 0; i < 8; i++) {
                    unsigned long long ap = pack2(av[i], av[i]);
                    fma2(accr[i][0], ap, bp0);
                    fma2(accr[i][1], ap, bp1);
                    fma2(accr[i][2], ap, bp2);
                    fma2(accr[i][3], ap, bp3);
                }
            }
            __syncthreads();
        }
    }

    // ---- epilogue: bias, optional ReLU, store ----
    float bcol[8];
#pragma unroll
    for (int j = 0; j < 8; j++) bcol[j] = bias[tx * 8 + j];

#pragma unroll
    for (int i = 0; i < 8; i++) {
        int r = row0 + ty * 8 + i;
        if (r >= nrows) continue;
        float o[8];
#pragma unroll
        for (int j = 0; j < 4; j++) {
            float2 v = unpack2(accr[i][j]);
            o[2 * j] = v.x;
            o[2 * j + 1] = v.y;
        }
#pragma unroll
        for (int j = 0; j < 8; j++) {
            o[j] += bcol[j];
            if (!LAYER1) o[j] = fmaxf(o[j], 0.f);  // ReLU after layer 0 only
        }
        float4* op = reinterpret_cast<float4*>(out + (size_t)r * D_ + tx * 8);
        op[0] = make_float4(o[0], o[1], o[2], o[3]);
        op[1] = make_float4(o[4], o[5], o[6], o[7]);
    }
}

// ---------------------------------------------------------------------------
// kernel_launch
//
// Inputs classified by element count (robust to metadata ordering; the
// within-category order is identical between setup_inputs dict order and the
// reference signature order):
//   NP*D=12,800,000 -> x_person         NQ*D=6,400,000 -> x_product
//   E=600,000 (x4)  -> src_pv, dst_pv, src_vp, dst_vp
//   D*D=16,384 (x8) -> Wl_pv0, Wr_pv0, Wl_vp0, Wr_vp0, Wl_pv1, Wr_pv1, Wl_vp1, Wr_vp1
//   D=128     (x4)  -> b_pv0, b_vp0, b_pv1, b_vp1
// Output: [h_p (NP*D) | h_q (NQ*D)]
// ---------------------------------------------------------------------------
extern "C" void kernel_launch(void* const* d_in, const int* in_sizes, int n_in,
                              void* d_out, int out_size)
{
    (void)out_size;
    const float* x_p = nullptr;
    const float* x_q = nullptr;
    const float* W[8] = {nullptr};
    const float* b[4] = {nullptr};
    const int*   eidx[4] = {nullptr};
    int wi = 0, bi = 0, ei = 0;
    int E = E_DEFAULT;

    for (int i = 0; i < n_in; i++) {
        int n = in_sizes[i];
        if (n == NP_ * D_)            x_p = (const float*)d_in[i];
        else if (n == NQ_ * D_)       x_q = (const float*)d_in[i];
        else if (n == D_ * D_)        { if (wi < 8) W[wi++] = (const float*)d_in[i]; }
        else if (n == D_)             { if (bi < 4) b[bi++] = (const float*)d_in[i]; }
        else                          { if (ei < 4) { eidx[ei++] = (const int*)d_in[i]; E = n; } }
    }

    const int* src_pv = eidx[0];
    const int* dst_pv = eidx[1];
    const int* src_vp = eidx[2];
    const int* dst_vp = eidx[3];
    float* out = (float*)d_out;

    int sblocks = (E * 32 + 255) / 256;           // one warp per edge
    dim3 gQ((NQ_ + BM - 1) / BM);
    dim3 gP((NP_ + BM - 1) / BM);

    // ---- Layer 0 ----
    zero_kernel<<<4096, 256>>>();
    scatter_kernel<true,  false><<<sblocks, 256>>>(x_p, src_pv, dst_pv, E);  // person -> product
    scatter_kernel<false, false><<<sblocks, 256>>>(x_q, src_vp, dst_vp, E);  // product -> person
    gemm_kernel<true,  false><<<gQ, 256>>>(x_q, W[0], W[1], b[0], nullptr, NQ_); // -> g_hQ (ReLU)
    gemm_kernel<false, false><<<gP, 256>>>(x_p, W[2], W[3], b[1], nullptr, NP_); // -> g_hP (ReLU)

    // ---- Layer 1 ----
    zero_kernel<<<4096, 256>>>();
    scatter_kernel<true,  true><<<sblocks, 256>>>(nullptr, src_pv, dst_pv, E); // g_hP -> product
    scatter_kernel<false, true><<<sblocks, 256>>>(nullptr, src_vp, dst_vp, E); // g_hQ -> person
    gemm_kernel<true,  true><<<gQ, 256>>>(nullptr, W[4], W[5], b[2],
                                          out + (size_t)NP_ * D_, NQ_);        // h_q
    gemm_kernel<false, true><<<gP, 256>>>(nullptr, W[6], W[7], b[3],
                                          out, NP_);                           // h_p
}